// round 8
// baseline (speedup 1.0000x reference)
#include <cuda_runtime.h>
#include <cuda_fp16.h>
#include <stdint.h>
#include <math.h>

#define TOK 2048
#define HID 1024
#define NEXP 8
#define INTER 4096
#define SOFTCAP 30.0f

// ---------------------------------------------------------------------------
// Device-global scratch
// ---------------------------------------------------------------------------
__device__ int    g_cnt[NEXP];
__device__ int    g_list[NEXP][TOK];
__device__ float  g_wl[NEXP][TOK];

__device__ __half g_xh[TOK * HID];
__device__ __half g_w2h[(size_t)NEXP * HID * INTER];
__device__ __half g_acth[(size_t)NEXP * TOK * INTER];

// ---------------------------------------------------------------------------
// PTX helpers (baseline ISA, valid on plain sm_103 target)
// ---------------------------------------------------------------------------
__device__ __forceinline__ uint32_t smem_u32(const void* p) {
    uint32_t a;
    asm("{ .reg .u64 t; cvta.to.shared.u64 t, %1; cvt.u32.u64 %0, t; }"
        : "=r"(a) : "l"(p));
    return a;
}

__device__ __forceinline__ void cpasync16(uint32_t smem, const void* g) {
    asm volatile("cp.async.cg.shared.global [%0], [%1], 16;"
                 :: "r"(smem), "l"(g) : "memory");
}
#define CP_COMMIT() asm volatile("cp.async.commit_group;" ::: "memory")
#define CP_WAIT(n)  asm volatile("cp.async.wait_group %0;" :: "n"(n) : "memory")

__device__ __forceinline__ void ldsm4(uint32_t* r, uint32_t addr) {
    asm volatile("ldmatrix.sync.aligned.m8n8.x4.shared.b16 {%0,%1,%2,%3}, [%4];"
                 : "=r"(r[0]), "=r"(r[1]), "=r"(r[2]), "=r"(r[3]) : "r"(addr));
}

__device__ __forceinline__ void mma16816(float* d, const uint32_t* a,
                                         const uint32_t* b) {
    asm volatile(
        "mma.sync.aligned.m16n8k16.row.col.f32.f16.f16.f32 "
        "{%0,%1,%2,%3}, {%4,%5,%6,%7}, {%8,%9}, {%0,%1,%2,%3};"
        : "+f"(d[0]), "+f"(d[1]), "+f"(d[2]), "+f"(d[3])
        : "r"(a[0]), "r"(a[1]), "r"(a[2]), "r"(a[3]), "r"(b[0]), "r"(b[1]));
}

__device__ __forceinline__ uint4 pack8(float4 a, float4 b) {
    __half2 h0 = __floats2half2_rn(a.x, a.y);
    __half2 h1 = __floats2half2_rn(a.z, a.w);
    __half2 h2 = __floats2half2_rn(b.x, b.y);
    __half2 h3 = __floats2half2_rn(b.z, b.w);
    uint4 u;
    u.x = *(uint32_t*)&h0; u.y = *(uint32_t*)&h1;
    u.z = *(uint32_t*)&h2; u.w = *(uint32_t*)&h3;
    return u;
}

// ---------------------------------------------------------------------------
// prep: convert x f32->f16, zero out, zero expert counters
// ---------------------------------------------------------------------------
__global__ void k_prep(const float4* __restrict__ x, __half* __restrict__ xh,
                       float4* __restrict__ out4, int n4) {
    int i = blockIdx.x * blockDim.x + threadIdx.x;
    if (blockIdx.x == 0 && threadIdx.x < NEXP) g_cnt[threadIdx.x] = 0;
    if (i >= n4) return;
    float4 v = x[i];
    __half2 h0 = __floats2half2_rn(v.x, v.y);
    __half2 h1 = __floats2half2_rn(v.z, v.w);
    uint2 u;
    u.x = *(uint32_t*)&h0;
    u.y = *(uint32_t*)&h1;
    *(uint2*)(xh + (size_t)i * 4) = u;
    out4[i] = make_float4(0.f, 0.f, 0.f, 0.f);
}

// ---------------------------------------------------------------------------
// Router
// ---------------------------------------------------------------------------
__global__ void k_router(const float* __restrict__ x, const float* __restrict__ wg) {
    const int t = blockIdx.x;
    const float* xr = x + (size_t)t * HID;

    float acc[NEXP];
#pragma unroll
    for (int e = 0; e < NEXP; e++) acc[e] = 0.0f;

    for (int h = threadIdx.x; h < HID; h += 128) {
        float xv = xr[h];
#pragma unroll
        for (int e = 0; e < NEXP; e++)
            acc[e] = fmaf(xv, wg[e * HID + h], acc[e]);
    }
#pragma unroll
    for (int o = 16; o > 0; o >>= 1) {
#pragma unroll
        for (int e = 0; e < NEXP; e++)
            acc[e] += __shfl_down_sync(0xffffffffu, acc[e], o);
    }

    __shared__ float red[4][NEXP];
    int wid = threadIdx.x >> 5;
    int lane = threadIdx.x & 31;
    if (lane == 0) {
#pragma unroll
        for (int e = 0; e < NEXP; e++) red[wid][e] = acc[e];
    }
    __syncthreads();

    if (threadIdx.x == 0) {
        float l[NEXP];
#pragma unroll
        for (int e = 0; e < NEXP; e++) {
            float v = red[0][e] + red[1][e] + red[2][e] + red[3][e];
            l[e] = SOFTCAP * tanhf(v * (1.0f / SOFTCAP));
        }
        int i0 = 0;
#pragma unroll
        for (int e = 1; e < NEXP; e++)
            if (l[e] > l[i0]) i0 = e;
        int i1 = (i0 == 0) ? 1 : 0;
#pragma unroll
        for (int e = 0; e < NEXP; e++)
            if (e != i0 && l[e] > l[i1]) i1 = e;

        float m = l[i0];
        float e0 = expf(l[i0] - m);
        float e1 = expf(l[i1] - m);
        float inv = 1.0f / (e0 + e1);

        int p0 = atomicAdd(&g_cnt[i0], 1);
        g_list[i0][p0] = t;
        g_wl[i0][p0] = e0 * inv;
        int p1 = atomicAdd(&g_cnt[i1], 1);
        g_list[i1][p1] = t;
        g_wl[i1][p1] = e1 * inv;
    }
}

// ---------------------------------------------------------------------------
// Fused gate+up GEMM with in-kernel f32->f16 weight conversion.
// act = gelu(X@w1^T) * (X@w3^T) -> fp16.
// CTA tile 128(M) x 64(N), K-chunk 64 over HID (16 chunks).
// A: f16 gathered rows, TRIPLE-buffered cp.async (issue(it+2) overlaps MMA(it)).
// B: f32 w1/w3 cp.async -> single-stage smem staging -> f16 tiles (2-stage).
// blockIdx.x in [16,20): w2 f32->f16 converter CTAs (overlap with GEMM wave).
// smem layout (bytes):
//   0      : rows[128] + pad (1024)
//   1024   : A f16, 3 x 16384
//   50176  : B1 f32 staging, 16384
//   66560  : B3 f32 staging, 16384
//   82944  : B1 f16, 2 x 8192
//   99328  : B3 f16, 2 x 8192   -> total 115712
// ---------------------------------------------------------------------------
#define OFF_A     1024u
#define OFF_STG1  50176u
#define OFF_STG3  66560u
#define OFF_FB1   82944u
#define OFF_FB3   99328u
#define G13_SMEM  115712
#define MTILES 16
#define CONVX 4

__global__ void __launch_bounds__(256, 2) k_g13(const __half* __restrict__ Xh,
                                                const float* __restrict__ W1,
                                                const float* __restrict__ W3,
                                                const float* __restrict__ W2f) {
    extern __shared__ char smem[];
    const int tid = threadIdx.x;

    // ---- converter CTAs: stream w2 f32 -> f16 (overlapped with GEMM) ----
    if (blockIdx.x >= MTILES) {
        int cid = ((blockIdx.x - MTILES) * gridDim.y + blockIdx.y) * gridDim.z
                  + blockIdx.z;                        // 0 .. 2047
        const int nconv = CONVX * (INTER / 64) * NEXP; // 2048
        const size_t n4 = (size_t)NEXP * HID * INTER / 4;
        size_t i = (size_t)cid * 256 + tid;
        const size_t stride = (size_t)nconv * 256;
        for (; i < n4; i += stride) {
            float4 v = ((const float4*)W2f)[i];
            __half2 h0 = __floats2half2_rn(v.x, v.y);
            __half2 h1 = __floats2half2_rn(v.z, v.w);
            uint2 u;
            u.x = *(uint32_t*)&h0;
            u.y = *(uint32_t*)&h1;
            *(uint2*)(g_w2h + i * 4) = u;
        }
        return;
    }

    const uint32_t sb = smem_u32(smem);
    int* rows_s = (int*)smem;

    const int e = blockIdx.z;
    const int cnt = g_cnt[e];
    const int m0 = blockIdx.x * 128;
    if (m0 >= cnt) return;
    const int n0 = blockIdx.y * 64;

    if (tid < 128) {
        int m = m0 + tid;
        rows_s[tid] = g_list[e][m < cnt ? m : cnt - 1];
    }
    __syncthreads();

    // A cp.async slots: row r0a+32i, 16B chunk kca
    const int r0a = tid >> 3;
    const int kca = tid & 7;
    const uint32_t aoff0 = ((uint32_t)r0a << 7) |
                           (((uint32_t)kca << 4) ^ (((uint32_t)(r0a & 7)) << 4));
    size_t arow[4];
#pragma unroll
    for (int i = 0; i < 4; i++)
        arow[i] = (size_t)rows_s[r0a + 32 * i] * HID + kca * 8;

    // B f32 staging slots: row r0b+16i (of 64), 16B chunk cb (of 16 per 256B row)
    const int r0b = tid >> 4;
    const int cb = tid & 15;
    const uint32_t stoff0 = (uint32_t)r0b * 256 + (uint32_t)cb * 16;
    const float* w1p = W1 + ((size_t)e * INTER + n0 + r0b) * HID + cb * 4;
    const float* w3p = W3 + ((size_t)e * INTER + n0 + r0b) * HID + cb * 4;

    // convert slots: f16 row rc+32s, chunk kcc
    const int rc = tid >> 3;
    const int kcc = tid & 7;
    const uint32_t cs0 = (uint32_t)rc * 256 + (uint32_t)kcc * 32;
    const uint32_t cf0 = ((uint32_t)rc << 7) |
                         (((uint32_t)kcc << 4) ^ (((uint32_t)(rc & 7)) << 4));

    const int lane = tid & 31;
    const int w = tid >> 5;
    const int mw = (w >> 2) * 64;
    const int nw = (w & 3) * 16;

    float acc1[4][2][4], acc3[4][2][4];
#pragma unroll
    for (int mi = 0; mi < 4; mi++)
#pragma unroll
        for (int nj = 0; nj < 2; nj++)
#pragma unroll
            for (int q = 0; q < 4; q++) { acc1[mi][nj][q] = 0.0f; acc3[mi][nj][q] = 0.0f; }

#define G13_ISSUE(c, ab)                                                        \
    do {                                                                        \
        _Pragma("unroll")                                                       \
        for (int i = 0; i < 4; i++)                                             \
            cpasync16(sb + OFF_A + (uint32_t)(ab) * 16384u + aoff0 + i * 4096u, \
                      Xh + arow[i] + ((c) << 6));                               \
        _Pragma("unroll")                                                       \
        for (int i = 0; i < 4; i++) {                                           \
            cpasync16(sb + OFF_STG1 + stoff0 + i * 4096u,                       \
                      w1p + (c) * 64 + (size_t)i * 16 * HID);                   \
            cpasync16(sb + OFF_STG3 + stoff0 + i * 4096u,                       \
                      w3p + (c) * 64 + (size_t)i * 16 * HID);                   \
        }                                                                       \
        CP_COMMIT();                                                            \
    } while (0)

#define G13_CONVERT(p)                                                          \
    do {                                                                        \
        _Pragma("unroll")                                                       \
        for (int s = 0; s < 2; s++) {                                           \
            float4 u1 = *(const float4*)(smem + OFF_STG1 + cs0 + s * 8192u);    \
            float4 v1 = *(const float4*)(smem + OFF_STG1 + cs0 + s * 8192u + 16);\
            *(uint4*)(smem + OFF_FB1 + (uint32_t)(p) * 8192u + cf0 + s * 4096u) \
                = pack8(u1, v1);                                                \
            float4 u3 = *(const float4*)(smem + OFF_STG3 + cs0 + s * 8192u);    \
            float4 v3 = *(const float4*)(smem + OFF_STG3 + cs0 + s * 8192u + 16);\
            *(uint4*)(smem + OFF_FB3 + (uint32_t)(p) * 8192u + cf0 + s * 4096u) \
                = pack8(u3, v3);                                                \
        }                                                                       \
    } while (0)

    // prologue: chunk 0 -> convert; issue chunk 1
    G13_ISSUE(0, 0);
    CP_WAIT(0);
    __syncthreads();
    G13_CONVERT(0);
    __syncthreads();
    G13_ISSUE(1, 1);

    int abuf = 0;
    const int nch = HID / 64;  // 16
    for (int it = 0; it < nch; it++) {
        if (it + 1 < nch) {
            CP_WAIT(0);
            __syncthreads();          // staging(it+1)+A(it+1) landed; MMA(it-1) done
            G13_CONVERT((it + 1) & 1);
            __syncthreads();          // staging free
            if (it + 2 < nch) {
                int ab2 = abuf + 2;
                if (ab2 >= 3) ab2 -= 3;
                G13_ISSUE(it + 2, ab2);  // overlaps MMA(it)
            }
        }

        const uint32_t aB = sb + OFF_A + (uint32_t)abuf * 16384u;
        const uint32_t b1B = sb + OFF_FB1 + ((it & 1) ? 8192u : 0u);
        const uint32_t b3B = sb + OFF_FB3 + ((it & 1) ? 8192u : 0u);
        const int mat = lane >> 3;

#pragma unroll
        for (int kk = 0; kk < 4; kk++) {
            uint32_t af[4][4];
#pragma unroll
            for (int mi = 0; mi < 4; mi++) {
                int row = mw + mi * 16 + (lane & 7) + (mat & 1) * 8;
                int kb = kk * 32 + (mat >> 1) * 16;
                uint32_t so = ((uint32_t)row << 7) |
                              ((uint32_t)kb ^ (((uint32_t)(row & 7)) << 4));
                ldsm4(af[mi], aB + so);
            }
            int brw = nw + (mat >> 1) * 8 + (lane & 7);
            int bkb = kk * 32 + (mat & 1) * 16;
            uint32_t bso = ((uint32_t)brw << 7) |
                           ((uint32_t)bkb ^ (((uint32_t)(brw & 7)) << 4));
            uint32_t bf1[4], bf3[4];
            ldsm4(bf1, b1B + bso);
            ldsm4(bf3, b3B + bso);
#pragma unroll
            for (int mi = 0; mi < 4; mi++) {
                mma16816(acc1[mi][0], af[mi], bf1 + 0);
                mma16816(acc1[mi][1], af[mi], bf1 + 2);
                mma16816(acc3[mi][0], af[mi], bf3 + 0);
                mma16816(acc3[mi][1], af[mi], bf3 + 2);
            }
        }
        abuf = (abuf == 2) ? 0 : abuf + 1;
    }

    // epilogue: act = gelu(h1) * h3 -> fp16, compact rows
#pragma unroll
    for (int mi = 0; mi < 4; mi++) {
        int m1 = m0 + mw + mi * 16 + (lane >> 2);
#pragma unroll
        for (int nj = 0; nj < 2; nj++) {
            int n = n0 + nw + nj * 8 + (lane & 3) * 2;
            __half* op = g_acth + ((size_t)e * TOK + m1) * INTER + n;
            if (m1 < cnt) {
                float a0 = acc1[mi][nj][0], a1 = acc1[mi][nj][1];
                float v0 = 0.5f * a0 * (1.0f + erff(a0 * 0.70710678118654752f)) * acc3[mi][nj][0];
                float v1 = 0.5f * a1 * (1.0f + erff(a1 * 0.70710678118654752f)) * acc3[mi][nj][1];
                *(__half2*)op = __floats2half2_rn(v0, v1);
            }
            if (m1 + 8 < cnt) {
                float a2 = acc1[mi][nj][2], a3 = acc1[mi][nj][3];
                float v2 = 0.5f * a2 * (1.0f + erff(a2 * 0.70710678118654752f)) * acc3[mi][nj][2];
                float v3 = 0.5f * a3 * (1.0f + erff(a3 * 0.70710678118654752f)) * acc3[mi][nj][3];
                *(__half2*)(op + (size_t)8 * INTER) = __floats2half2_rn(v2, v3);
            }
        }
    }
}

// ---------------------------------------------------------------------------
// GEMM2: out[token] += w * (act @ w2^T) via f32 atomics. CTA 128x64, K=INTER.
// ---------------------------------------------------------------------------
#define G2_SMEM (1024 + 32768 + 16384)

__global__ void __launch_bounds__(256, 3) k_g2(const __half* __restrict__ W2,
                                               float* __restrict__ out) {
    extern __shared__ char smem[];
    const uint32_t sb = smem_u32(smem);
    int* tok_s = (int*)smem;             // [128]
    float* wt_s = (float*)(smem + 512);  // [128]

    const int e = blockIdx.z;
    const int cnt = g_cnt[e];
    const int m0 = blockIdx.x * 128;
    if (m0 >= cnt) return;
    const int n0 = blockIdx.y * 64;

    const int tid = threadIdx.x;
    if (tid < 128) {
        int m = m0 + tid;
        int mi2 = m < cnt ? m : cnt - 1;
        tok_s[tid] = g_list[e][mi2];
        wt_s[tid] = g_wl[e][mi2];
    }
    __syncthreads();

    const uint32_t sA = sb + 1024;
    const uint32_t sB = sb + 1024 + 32768;

    size_t arow[4];
    uint32_t aoff[4];
#pragma unroll
    for (int i = 0; i < 4; i++) {
        int lin = tid + 256 * i;
        int r = lin >> 3;
        int kc = lin & 7;
        aoff[i] = ((uint32_t)r << 7) | (((uint32_t)kc << 4) ^ (((uint32_t)(r & 7)) << 4));
        arow[i] = ((size_t)e * TOK + m0 + r) * INTER + kc * 8;
    }
    size_t brow[2];
    uint32_t boff[2];
#pragma unroll
    for (int s = 0; s < 2; s++) {
        int p = tid + 256 * s;
        int r = p >> 3;
        int kc = p & 7;
        boff[s] = ((uint32_t)r << 7) | (((uint32_t)kc << 4) ^ (((uint32_t)(r & 7)) << 4));
        brow[s] = ((size_t)e * HID + n0 + r) * INTER + kc * 8;
    }

    const int lane = tid & 31;
    const int w = tid >> 5;
    const int mw = (w >> 2) * 64;
    const int nw = (w & 3) * 16;

    float acc[4][2][4];
#pragma unroll
    for (int mi = 0; mi < 4; mi++)
#pragma unroll
        for (int nj = 0; nj < 2; nj++)
#pragma unroll
            for (int q = 0; q < 4; q++) acc[mi][nj][q] = 0.0f;

#pragma unroll
    for (int i = 0; i < 4; i++) cpasync16(sA + aoff[i], g_acth + arow[i]);
#pragma unroll
    for (int s = 0; s < 2; s++) cpasync16(sB + boff[s], W2 + brow[s]);
    CP_COMMIT();

    const int nch = INTER / 64;  // 64
    for (int it = 0; it < nch; it++) {
        if (it + 1 < nch) {
            const int k0 = (it + 1) << 6;
            const uint32_t sg = ((it + 1) & 1) ? 1u : 0u;
#pragma unroll
            for (int i = 0; i < 4; i++)
                cpasync16(sA + sg * 16384u + aoff[i], g_acth + arow[i] + k0);
#pragma unroll
            for (int s = 0; s < 2; s++)
                cpasync16(sB + sg * 8192u + boff[s], W2 + brow[s] + k0);
            CP_COMMIT();
            CP_WAIT(1);
        } else {
            CP_WAIT(0);
        }
        __syncthreads();

        const uint32_t aB = sA + ((it & 1) ? 16384u : 0u);
        const uint32_t bB = sB + ((it & 1) ? 8192u : 0u);
        const int mat = lane >> 3;

#pragma unroll
        for (int kk = 0; kk < 4; kk++) {
            uint32_t af[4][4];
#pragma unroll
            for (int mi = 0; mi < 4; mi++) {
                int row = mw + mi * 16 + (lane & 7) + (mat & 1) * 8;
                int kb = kk * 32 + (mat >> 1) * 16;
                uint32_t so = ((uint32_t)row << 7) |
                              ((uint32_t)kb ^ (((uint32_t)(row & 7)) << 4));
                ldsm4(af[mi], aB + so);
            }
            int brw = nw + (mat >> 1) * 8 + (lane & 7);
            int bkb = kk * 32 + (mat & 1) * 16;
            uint32_t bso = ((uint32_t)brw << 7) |
                           ((uint32_t)bkb ^ (((uint32_t)(brw & 7)) << 4));
            uint32_t bf[4];
            ldsm4(bf, bB + bso);
#pragma unroll
            for (int mi = 0; mi < 4; mi++) {
                mma16816(acc[mi][0], af[mi], bf + 0);
                mma16816(acc[mi][1], af[mi], bf + 2);
            }
        }
        __syncthreads();
    }

    // epilogue: weighted atomic scatter-add into out
#pragma unroll
    for (int mi = 0; mi < 4; mi++) {
        int mm = mw + mi * 16 + (lane >> 2);
        int m1 = m0 + mm;
#pragma unroll
        for (int nj = 0; nj < 2; nj++) {
            int n = n0 + nw + nj * 8 + (lane & 3) * 2;
            if (m1 < cnt) {
                int t = tok_s[mm];
                float ww = wt_s[mm];
                float* op = out + (size_t)t * HID + n;
                atomicAdd(op + 0, ww * acc[mi][nj][0]);
                atomicAdd(op + 1, ww * acc[mi][nj][1]);
            }
            if (m1 + 8 < cnt) {
                int t = tok_s[mm + 8];
                float ww = wt_s[mm + 8];
                float* op = out + (size_t)t * HID + n;
                atomicAdd(op + 0, ww * acc[mi][nj][2]);
                atomicAdd(op + 1, ww * acc[mi][nj][3]);
            }
        }
    }
}

// ---------------------------------------------------------------------------
// launch
// ---------------------------------------------------------------------------
extern "C" void kernel_launch(void* const* d_in, const int* in_sizes, int n_in,
                              void* d_out, int out_size) {
    const float* x  = (const float*)d_in[0];
    const float* wg = (const float*)d_in[1];
    const float* w1 = (const float*)d_in[2];
    const float* w3 = (const float*)d_in[3];
    const float* w2 = (const float*)d_in[4];
    float* out = (float*)d_out;

    cudaFuncSetAttribute(k_g13, cudaFuncAttributeMaxDynamicSharedMemorySize, G13_SMEM);
    cudaFuncSetAttribute(k_g2, cudaFuncAttributeMaxDynamicSharedMemorySize, G2_SMEM);

    __half *xh, *w2h;
    cudaGetSymbolAddress((void**)&xh, g_xh);
    cudaGetSymbolAddress((void**)&w2h, g_w2h);

    const int n4 = TOK * HID / 4;
    k_prep<<<(n4 + 255) / 256, 256>>>((const float4*)x, xh, (float4*)out, n4);
    k_router<<<TOK, 128>>>(x, wg);

    // x-dim: [0,16) GEMM m-tiles, [16,20) w2 converter CTAs (overlapped)
    k_g13<<<dim3(MTILES + CONVX, INTER / 64, NEXP), 256, G13_SMEM>>>(xh, w1, w3, w2);
    k_g2<<<dim3(TOK / 128, HID / 64, NEXP), 256, G2_SMEM>>>(w2h, out);
}

// round 9
// speedup vs baseline: 1.0443x; 1.0443x over previous
#include <cuda_runtime.h>
#include <cuda_fp16.h>
#include <stdint.h>
#include <math.h>

#define TOK 2048
#define HID 1024
#define NEXP 8
#define INTER 4096
#define SOFTCAP 30.0f

// ---------------------------------------------------------------------------
// Device-global scratch
// ---------------------------------------------------------------------------
__device__ int    g_cnt[NEXP];
__device__ int    g_list[NEXP][TOK];
__device__ float  g_wl[NEXP][TOK];

__device__ __half g_xh[TOK * HID];
__device__ __half g_w1h[(size_t)NEXP * INTER * HID];
__device__ __half g_w3h[(size_t)NEXP * INTER * HID];
__device__ __half g_w2h[(size_t)NEXP * HID * INTER];
__device__ __half g_acth[(size_t)NEXP * TOK * INTER];

// ---------------------------------------------------------------------------
// PTX helpers (baseline ISA, valid on plain sm_103 target)
// ---------------------------------------------------------------------------
__device__ __forceinline__ uint32_t smem_u32(const void* p) {
    uint32_t a;
    asm("{ .reg .u64 t; cvta.to.shared.u64 t, %1; cvt.u32.u64 %0, t; }"
        : "=r"(a) : "l"(p));
    return a;
}

__device__ __forceinline__ void cpasync16(uint32_t smem, const void* g) {
    asm volatile("cp.async.cg.shared.global [%0], [%1], 16;"
                 :: "r"(smem), "l"(g) : "memory");
}
#define CP_COMMIT() asm volatile("cp.async.commit_group;" ::: "memory")
#define CP_WAIT(n)  asm volatile("cp.async.wait_group %0;" :: "n"(n) : "memory")

__device__ __forceinline__ void ldsm4(uint32_t* r, uint32_t addr) {
    asm volatile("ldmatrix.sync.aligned.m8n8.x4.shared.b16 {%0,%1,%2,%3}, [%4];"
                 : "=r"(r[0]), "=r"(r[1]), "=r"(r[2]), "=r"(r[3]) : "r"(addr));
}

__device__ __forceinline__ void mma16816(float* d, const uint32_t* a,
                                         const uint32_t* b) {
    asm volatile(
        "mma.sync.aligned.m16n8k16.row.col.f32.f16.f16.f32 "
        "{%0,%1,%2,%3}, {%4,%5,%6,%7}, {%8,%9}, {%0,%1,%2,%3};"
        : "+f"(d[0]), "+f"(d[1]), "+f"(d[2]), "+f"(d[3])
        : "r"(a[0]), "r"(a[1]), "r"(a[2]), "r"(a[3]), "r"(b[0]), "r"(b[1]));
}

// ---------------------------------------------------------------------------
// prep: convert x f32->f16, zero out, zero expert counters
// ---------------------------------------------------------------------------
__global__ void k_prep(const float4* __restrict__ x, __half* __restrict__ xh,
                       float4* __restrict__ out4, int n4) {
    int i = blockIdx.x * blockDim.x + threadIdx.x;
    if (blockIdx.x == 0 && threadIdx.x < NEXP) g_cnt[threadIdx.x] = 0;
    if (i >= n4) return;
    float4 v = x[i];
    __half2 h0 = __floats2half2_rn(v.x, v.y);
    __half2 h1 = __floats2half2_rn(v.z, v.w);
    uint2 u;
    u.x = *(uint32_t*)&h0;
    u.y = *(uint32_t*)&h1;
    *(uint2*)(xh + (size_t)i * 4) = u;
    out4[i] = make_float4(0.f, 0.f, 0.f, 0.f);
}

// ---------------------------------------------------------------------------
// w1 + w3 conversion in one launch
// ---------------------------------------------------------------------------
__global__ void k_convw(const float4* __restrict__ w1, const float4* __restrict__ w3,
                        __half* __restrict__ w1h, __half* __restrict__ w3h, int n4) {
    int i = blockIdx.x * blockDim.x + threadIdx.x;
    const float4* src;
    __half* dst;
    if (i < n4) { src = w1; dst = w1h; }
    else        { src = w3; dst = w3h; i -= n4; }
    float4 v = src[i];
    __half2 h0 = __floats2half2_rn(v.x, v.y);
    __half2 h1 = __floats2half2_rn(v.z, v.w);
    uint2 u;
    u.x = *(uint32_t*)&h0;
    u.y = *(uint32_t*)&h1;
    *(uint2*)(dst + (size_t)i * 4) = u;
}

// ---------------------------------------------------------------------------
// Router
// ---------------------------------------------------------------------------
__global__ void k_router(const float* __restrict__ x, const float* __restrict__ wg) {
    const int t = blockIdx.x;
    const float* xr = x + (size_t)t * HID;

    float acc[NEXP];
#pragma unroll
    for (int e = 0; e < NEXP; e++) acc[e] = 0.0f;

    for (int h = threadIdx.x; h < HID; h += 128) {
        float xv = xr[h];
#pragma unroll
        for (int e = 0; e < NEXP; e++)
            acc[e] = fmaf(xv, wg[e * HID + h], acc[e]);
    }
#pragma unroll
    for (int o = 16; o > 0; o >>= 1) {
#pragma unroll
        for (int e = 0; e < NEXP; e++)
            acc[e] += __shfl_down_sync(0xffffffffu, acc[e], o);
    }

    __shared__ float red[4][NEXP];
    int wid = threadIdx.x >> 5;
    int lane = threadIdx.x & 31;
    if (lane == 0) {
#pragma unroll
        for (int e = 0; e < NEXP; e++) red[wid][e] = acc[e];
    }
    __syncthreads();

    if (threadIdx.x == 0) {
        float l[NEXP];
#pragma unroll
        for (int e = 0; e < NEXP; e++) {
            float v = red[0][e] + red[1][e] + red[2][e] + red[3][e];
            l[e] = SOFTCAP * tanhf(v * (1.0f / SOFTCAP));
        }
        int i0 = 0;
#pragma unroll
        for (int e = 1; e < NEXP; e++)
            if (l[e] > l[i0]) i0 = e;
        int i1 = (i0 == 0) ? 1 : 0;
#pragma unroll
        for (int e = 0; e < NEXP; e++)
            if (e != i0 && l[e] > l[i1]) i1 = e;

        float m = l[i0];
        float e0 = expf(l[i0] - m);
        float e1 = expf(l[i1] - m);
        float inv = 1.0f / (e0 + e1);

        int p0 = atomicAdd(&g_cnt[i0], 1);
        g_list[i0][p0] = t;
        g_wl[i0][p0] = e0 * inv;
        int p1 = atomicAdd(&g_cnt[i1], 1);
        g_list[i1][p1] = t;
        g_wl[i1][p1] = e1 * inv;
    }
}

// ---------------------------------------------------------------------------
// Fused gate+up GEMM (f16 operands): act = gelu(X@w1^T) * (X@w3^T) -> fp16
// CTA tile 128(M) x 64(N), K-chunk 64 over HID (16 chunks), 3-STAGE cp.async.
// blockIdx.x in [16,20): w2 f32->f16 converter CTAs (overlap with GEMM wave).
// smem: header 1024 | A 3x16384 | B1 3x8192 | B3 3x8192 = 99328
// ---------------------------------------------------------------------------
#define G13_SMEM 99328
#define MTILES 16
#define CONVX 4

__global__ void __launch_bounds__(256, 2) k_g13(const __half* __restrict__ Xh,
                                                const __half* __restrict__ W1,
                                                const __half* __restrict__ W3,
                                                const float* __restrict__ W2f) {
    extern __shared__ char smem[];
    const int tid = threadIdx.x;

    // ---- converter CTAs: stream w2 f32 -> f16 (overlapped with GEMM) ----
    if (blockIdx.x >= MTILES) {
        int cid = ((blockIdx.x - MTILES) * gridDim.y + blockIdx.y) * gridDim.z
                  + blockIdx.z;                        // 0 .. 2047
        const int nconv = CONVX * (INTER / 64) * NEXP; // 2048
        const size_t n4 = (size_t)NEXP * HID * INTER / 4;
        size_t i = (size_t)cid * 256 + tid;
        const size_t stride = (size_t)nconv * 256;
        for (; i < n4; i += stride) {
            float4 v = ((const float4*)W2f)[i];
            __half2 h0 = __floats2half2_rn(v.x, v.y);
            __half2 h1 = __floats2half2_rn(v.z, v.w);
            uint2 u;
            u.x = *(uint32_t*)&h0;
            u.y = *(uint32_t*)&h1;
            *(uint2*)(g_w2h + i * 4) = u;
        }
        return;
    }

    const uint32_t sb = smem_u32(smem);
    int* rows_s = (int*)smem;

    const int e = blockIdx.z;
    const int cnt = g_cnt[e];
    const int m0 = blockIdx.x * 128;
    if (m0 >= cnt) return;
    const int n0 = blockIdx.y * 64;

    if (tid < 128) {
        int m = m0 + tid;
        rows_s[tid] = g_list[e][m < cnt ? m : cnt - 1];
    }
    __syncthreads();

    const uint32_t sA = sb + 1024;       // 3 x 16384
    const uint32_t sB1 = sb + 50176;     // 3 x 8192
    const uint32_t sB3 = sb + 74752;     // 3 x 8192

    size_t arow[4];
    uint32_t aoff[4];
#pragma unroll
    for (int i = 0; i < 4; i++) {
        int lin = tid + 256 * i;
        int r = lin >> 3;
        int kc = lin & 7;
        aoff[i] = ((uint32_t)r << 7) | (((uint32_t)kc << 4) ^ (((uint32_t)(r & 7)) << 4));
        arow[i] = (size_t)rows_s[r] * HID + kc * 8;
    }
    size_t brow[2];
    uint32_t boff[2];
#pragma unroll
    for (int s = 0; s < 2; s++) {
        int p = tid + 256 * s;
        int r = p >> 3;
        int kc = p & 7;
        boff[s] = ((uint32_t)r << 7) | (((uint32_t)kc << 4) ^ (((uint32_t)(r & 7)) << 4));
        brow[s] = ((size_t)e * INTER + n0 + r) * HID + kc * 8;
    }

    const int lane = tid & 31;
    const int w = tid >> 5;
    const int mw = (w >> 2) * 64;   // 0 or 64
    const int nw = (w & 3) * 16;    // 0,16,32,48

    float acc1[4][2][4], acc3[4][2][4];
#pragma unroll
    for (int mi = 0; mi < 4; mi++)
#pragma unroll
        for (int nj = 0; nj < 2; nj++)
#pragma unroll
            for (int q = 0; q < 4; q++) { acc1[mi][nj][q] = 0.0f; acc3[mi][nj][q] = 0.0f; }

#define G13_ISSUE(c, buf)                                                      \
    do {                                                                       \
        const uint32_t aS = sA + (uint32_t)(buf) * 16384u;                     \
        const uint32_t b1S = sB1 + (uint32_t)(buf) * 8192u;                    \
        const uint32_t b3S = sB3 + (uint32_t)(buf) * 8192u;                    \
        const int k0 = (c) << 6;                                               \
        _Pragma("unroll")                                                      \
        for (int i = 0; i < 4; i++)                                            \
            cpasync16(aS + aoff[i], Xh + arow[i] + k0);                        \
        _Pragma("unroll")                                                      \
        for (int s = 0; s < 2; s++) {                                          \
            cpasync16(b1S + boff[s], W1 + brow[s] + k0);                       \
            cpasync16(b3S + boff[s], W3 + brow[s] + k0);                       \
        }                                                                      \
        CP_COMMIT();                                                           \
    } while (0)

    // prologue: issue chunks 0 and 1
    G13_ISSUE(0, 0);
    G13_ISSUE(1, 1);

    int ab = 0;
    const int nch = HID / 64;  // 16
    for (int it = 0; it < nch; it++) {
        if (it + 1 < nch) { CP_WAIT(1); } else { CP_WAIT(0); }
        __syncthreads();  // chunk `it` visible; MMA(it-1) finished in all warps
        if (it + 2 < nch) {
            int nb = ab + 2;
            if (nb >= 3) nb -= 3;
            G13_ISSUE(it + 2, nb);  // lands during MMA(it) + MMA(it+1)
        }

        const uint32_t aB = sA + (uint32_t)ab * 16384u;
        const uint32_t b1B = sB1 + (uint32_t)ab * 8192u;
        const uint32_t b3B = sB3 + (uint32_t)ab * 8192u;
        const int mat = lane >> 3;

#pragma unroll
        for (int kk = 0; kk < 4; kk++) {
            uint32_t af[4][4];
#pragma unroll
            for (int mi = 0; mi < 4; mi++) {
                int row = mw + mi * 16 + (lane & 7) + (mat & 1) * 8;
                int kb = kk * 32 + (mat >> 1) * 16;
                uint32_t so = ((uint32_t)row << 7) |
                              ((uint32_t)kb ^ (((uint32_t)(row & 7)) << 4));
                ldsm4(af[mi], aB + so);
            }
            int brw = nw + (mat >> 1) * 8 + (lane & 7);
            int bkb = kk * 32 + (mat & 1) * 16;
            uint32_t bso = ((uint32_t)brw << 7) |
                           ((uint32_t)bkb ^ (((uint32_t)(brw & 7)) << 4));
            uint32_t bf1[4], bf3[4];
            ldsm4(bf1, b1B + bso);
            ldsm4(bf3, b3B + bso);
#pragma unroll
            for (int mi = 0; mi < 4; mi++) {
                mma16816(acc1[mi][0], af[mi], bf1 + 0);
                mma16816(acc1[mi][1], af[mi], bf1 + 2);
                mma16816(acc3[mi][0], af[mi], bf3 + 0);
                mma16816(acc3[mi][1], af[mi], bf3 + 2);
            }
        }
        ab = (ab == 2) ? 0 : ab + 1;
    }

    // epilogue: act = gelu(h1) * h3 -> fp16, compact rows
#pragma unroll
    for (int mi = 0; mi < 4; mi++) {
        int m1 = m0 + mw + mi * 16 + (lane >> 2);
#pragma unroll
        for (int nj = 0; nj < 2; nj++) {
            int n = n0 + nw + nj * 8 + (lane & 3) * 2;
            __half* op = g_acth + ((size_t)e * TOK + m1) * INTER + n;
            if (m1 < cnt) {
                float a0 = acc1[mi][nj][0], a1 = acc1[mi][nj][1];
                float v0 = 0.5f * a0 * (1.0f + erff(a0 * 0.70710678118654752f)) * acc3[mi][nj][0];
                float v1 = 0.5f * a1 * (1.0f + erff(a1 * 0.70710678118654752f)) * acc3[mi][nj][1];
                *(__half2*)op = __floats2half2_rn(v0, v1);
            }
            if (m1 + 8 < cnt) {
                float a2 = acc1[mi][nj][2], a3 = acc1[mi][nj][3];
                float v2 = 0.5f * a2 * (1.0f + erff(a2 * 0.70710678118654752f)) * acc3[mi][nj][2];
                float v3 = 0.5f * a3 * (1.0f + erff(a3 * 0.70710678118654752f)) * acc3[mi][nj][3];
                *(__half2*)(op + (size_t)8 * INTER) = __floats2half2_rn(v2, v3);
            }
        }
    }
}

// ---------------------------------------------------------------------------
// GEMM2: out[token] += w * (act @ w2^T), f32 atomics.
// CTA tile 128x64, K-SPLIT=4 (each CTA: K range of 1024, 16 chunks), 3-stage.
// grid: x = m-tiles (16), y = n-tile(16) | ksplit(4) -> 64, z = expert.
// smem: header 1024 | A 3x16384 | B 3x8192 = 74752 ; 3 CTAs/SM.
// ---------------------------------------------------------------------------
#define G2_SMEM 74752
#define KSPLIT 4

__global__ void __launch_bounds__(256, 3) k_g2(const __half* __restrict__ W2,
                                               float* __restrict__ out) {
    extern __shared__ char smem[];
    const uint32_t sb = smem_u32(smem);
    int* tok_s = (int*)smem;             // [128]
    float* wt_s = (float*)(smem + 512);  // [128]

    const int e = blockIdx.z;
    const int cnt = g_cnt[e];
    const int m0 = blockIdx.x * 128;
    if (m0 >= cnt) return;
    const int n0 = (blockIdx.y & 15) * 64;
    const int kbase = (blockIdx.y >> 4) * (INTER / KSPLIT);  // 0,1024,2048,3072

    const int tid = threadIdx.x;
    if (tid < 128) {
        int m = m0 + tid;
        int mi2 = m < cnt ? m : cnt - 1;
        tok_s[tid] = g_list[e][mi2];
        wt_s[tid] = g_wl[e][mi2];
    }
    __syncthreads();

    const uint32_t sA = sb + 1024;    // 3 x 16384
    const uint32_t sB = sb + 50176;   // 3 x 8192

    size_t arow[4];
    uint32_t aoff[4];
#pragma unroll
    for (int i = 0; i < 4; i++) {
        int lin = tid + 256 * i;
        int r = lin >> 3;
        int kc = lin & 7;
        aoff[i] = ((uint32_t)r << 7) | (((uint32_t)kc << 4) ^ (((uint32_t)(r & 7)) << 4));
        arow[i] = ((size_t)e * TOK + m0 + r) * INTER + kbase + kc * 8;
    }
    size_t brow[2];
    uint32_t boff[2];
#pragma unroll
    for (int s = 0; s < 2; s++) {
        int p = tid + 256 * s;
        int r = p >> 3;
        int kc = p & 7;
        boff[s] = ((uint32_t)r << 7) | (((uint32_t)kc << 4) ^ (((uint32_t)(r & 7)) << 4));
        brow[s] = ((size_t)e * HID + n0 + r) * INTER + kbase + kc * 8;
    }

    const int lane = tid & 31;
    const int w = tid >> 5;
    const int mw = (w >> 2) * 64;
    const int nw = (w & 3) * 16;

    float acc[4][2][4];
#pragma unroll
    for (int mi = 0; mi < 4; mi++)
#pragma unroll
        for (int nj = 0; nj < 2; nj++)
#pragma unroll
            for (int q = 0; q < 4; q++) acc[mi][nj][q] = 0.0f;

#define G2_ISSUE(c, buf)                                                       \
    do {                                                                       \
        const uint32_t aS = sA + (uint32_t)(buf) * 16384u;                     \
        const uint32_t bS = sB + (uint32_t)(buf) * 8192u;                      \
        const int k0 = (c) << 6;                                               \
        _Pragma("unroll")                                                      \
        for (int i = 0; i < 4; i++)                                            \
            cpasync16(aS + aoff[i], g_acth + arow[i] + k0);                    \
        _Pragma("unroll")                                                      \
        for (int s = 0; s < 2; s++)                                            \
            cpasync16(bS + boff[s], W2 + brow[s] + k0);                        \
        CP_COMMIT();                                                           \
    } while (0)

    G2_ISSUE(0, 0);
    G2_ISSUE(1, 1);

    int ab = 0;
    const int nch = (INTER / KSPLIT) / 64;  // 16
    for (int it = 0; it < nch; it++) {
        if (it + 1 < nch) { CP_WAIT(1); } else { CP_WAIT(0); }
        __syncthreads();
        if (it + 2 < nch) {
            int nb = ab + 2;
            if (nb >= 3) nb -= 3;
            G2_ISSUE(it + 2, nb);
        }

        const uint32_t aB = sA + (uint32_t)ab * 16384u;
        const uint32_t bB = sB + (uint32_t)ab * 8192u;
        const int mat = lane >> 3;

#pragma unroll
        for (int kk = 0; kk < 4; kk++) {
            uint32_t af[4][4];
#pragma unroll
            for (int mi = 0; mi < 4; mi++) {
                int row = mw + mi * 16 + (lane & 7) + (mat & 1) * 8;
                int kb = kk * 32 + (mat >> 1) * 16;
                uint32_t so = ((uint32_t)row << 7) |
                              ((uint32_t)kb ^ (((uint32_t)(row & 7)) << 4));
                ldsm4(af[mi], aB + so);
            }
            int brw = nw + (mat >> 1) * 8 + (lane & 7);
            int bkb = kk * 32 + (mat & 1) * 16;
            uint32_t bso = ((uint32_t)brw << 7) |
                           ((uint32_t)bkb ^ (((uint32_t)(brw & 7)) << 4));
            uint32_t bf[4];
            ldsm4(bf, bB + bso);
#pragma unroll
            for (int mi = 0; mi < 4; mi++) {
                mma16816(acc[mi][0], af[mi], bf + 0);
                mma16816(acc[mi][1], af[mi], bf + 2);
            }
        }
        ab = (ab == 2) ? 0 : ab + 1;
    }

    // epilogue: weighted atomic scatter-add into out
#pragma unroll
    for (int mi = 0; mi < 4; mi++) {
        int mm = mw + mi * 16 + (lane >> 2);
        int m1 = m0 + mm;
#pragma unroll
        for (int nj = 0; nj < 2; nj++) {
            int n = n0 + nw + nj * 8 + (lane & 3) * 2;
            if (m1 < cnt) {
                int t = tok_s[mm];
                float ww = wt_s[mm];
                float* op = out + (size_t)t * HID + n;
                atomicAdd(op + 0, ww * acc[mi][nj][0]);
                atomicAdd(op + 1, ww * acc[mi][nj][1]);
            }
            if (m1 + 8 < cnt) {
                int t = tok_s[mm + 8];
                float ww = wt_s[mm + 8];
                float* op = out + (size_t)t * HID + n;
                atomicAdd(op + 0, ww * acc[mi][nj][2]);
                atomicAdd(op + 1, ww * acc[mi][nj][3]);
            }
        }
    }
}

// ---------------------------------------------------------------------------
// launch
// ---------------------------------------------------------------------------
extern "C" void kernel_launch(void* const* d_in, const int* in_sizes, int n_in,
                              void* d_out, int out_size) {
    const float* x  = (const float*)d_in[0];
    const float* wg = (const float*)d_in[1];
    const float* w1 = (const float*)d_in[2];
    const float* w3 = (const float*)d_in[3];
    const float* w2 = (const float*)d_in[4];
    float* out = (float*)d_out;

    cudaFuncSetAttribute(k_g13, cudaFuncAttributeMaxDynamicSharedMemorySize, G13_SMEM);
    cudaFuncSetAttribute(k_g2, cudaFuncAttributeMaxDynamicSharedMemorySize, G2_SMEM);

    __half *xh, *w1h, *w3h, *w2h;
    cudaGetSymbolAddress((void**)&xh, g_xh);
    cudaGetSymbolAddress((void**)&w1h, g_w1h);
    cudaGetSymbolAddress((void**)&w3h, g_w3h);
    cudaGetSymbolAddress((void**)&w2h, g_w2h);

    const int n4 = TOK * HID / 4;
    const int nw4 = (int)((size_t)NEXP * INTER * HID / 4);
    k_prep<<<(n4 + 255) / 256, 256>>>((const float4*)x, xh, (float4*)out, n4);
    k_router<<<TOK, 128>>>(x, wg);
    k_convw<<<(2 * nw4) / 256, 256>>>((const float4*)w1, (const float4*)w3, w1h, w3h, nw4);

    // x-dim: [0,16) GEMM m-tiles, [16,20) w2 converter CTAs (overlapped)
    k_g13<<<dim3(MTILES + CONVX, INTER / 64, NEXP), 256, G13_SMEM>>>(xh, w1h, w3h, w2);
    k_g2<<<dim3(TOK / 128, 16 * KSPLIT, NEXP), 256, G2_SMEM>>>(w2h, out);
}